// round 9
// baseline (speedup 1.0000x reference)
#include <cuda_runtime.h>

#define NB      8
#define NCH     19
#define HWSZ    (512*512)
#define NDIM    768
#define NCLS    1000
#define NSLOT   54
#define TOTAL_CTAS (NB * (NSLOT + 1))   // 440 <= 148*3 : single wave @occ3
#define NGROUPS (HWSZ/4)

// per-block partials: [b][slot][ 0..18 inter | 19..37 psum | 38..56 cnt | 57 focal | pad ]
__device__ float g_part[NB][NSLOT][60];
__device__ float g_misc[24];            // ce[8] | vinv[8] | tinv[8]
__device__ int   g_count;               // static zero-init; last CTA resets it

__device__ __forceinline__ float fast_exp(float x) {
    // exp(x) = 2^(x*log2e); FMA-fused magic round; splice uses fz bits directly
    const float L2E = 1.4426950408889634f;
    float fz = fmaf(x, L2E, 12582912.0f);
    float fm = fz - 12582912.0f;
    float r  = fmaf(x, L2E, -fm);               // r in [-0.5, 0.5]
    float p  = 9.6181291e-3f;
    p = fmaf(p, r, 5.5504109e-2f);
    p = fmaf(p, r, 2.4022651e-1f);
    p = fmaf(p, r, 6.9314718e-1f);
    p = fmaf(p, r, 1.0f);
    return __int_as_float(__float_as_int(p) + (__float_as_int(fz) << 23));
}

__global__ __launch_bounds__(256, 3) void fused_kernel(
    const float* __restrict__ seg,    const int* __restrict__ gt,
    const float* __restrict__ logits, const int* __restrict__ label,
    const float* __restrict__ vf,     const float* __restrict__ tf,
    const float* __restrict__ mm,     const int* __restrict__ ep,
    float* __restrict__ out)
{
    const int b  = blockIdx.y;
    const int bx = blockIdx.x;
    const unsigned FULL = 0xffffffffu;
    const int tid  = threadIdx.x;
    const int lane = tid & 31;
    const int w    = tid >> 5;

    if (bx == NSLOT) {
        // ── misc CTA (one per batch row): CE + feature norms ──
        float ce_p = 0.f, sv = 0.f, st = 0.f;
        if (tid < NCLS/4) {
            float4 L = ((const float4*)(logits + b*NCLS))[tid];
            ce_p = (__expf(L.x) + __expf(L.y)) + (__expf(L.z) + __expf(L.w));
        }
        if (tid < NDIM/4) {
            float4 V = ((const float4*)(vf + b*NDIM))[tid];
            sv = fmaf(V.x,V.x, fmaf(V.y,V.y, fmaf(V.z,V.z, V.w*V.w)));
            float4 T = ((const float4*)(tf + b*NDIM))[tid];
            st = fmaf(T.x,T.x, fmaf(T.y,T.y, fmaf(T.z,T.z, T.w*T.w)));
        }
#pragma unroll
        for (int o = 16; o > 0; o >>= 1) {
            ce_p += __shfl_down_sync(FULL, ce_p, o);
            sv   += __shfl_down_sync(FULL, sv, o);
            st   += __shfl_down_sync(FULL, st, o);
        }
        __shared__ float shm[8][3];
        if (lane == 0) { shm[w][0] = ce_p; shm[w][1] = sv; shm[w][2] = st; }
        __syncthreads();
        if (tid == 0) {
            float s = 0.f, a = 0.f, c = 0.f;
#pragma unroll
            for (int i = 0; i < 8; i++) { s += shm[i][0]; a += shm[i][1]; c += shm[i][2]; }
            g_misc[b]      = __logf(s) - logits[b*NCLS + label[b]];
            g_misc[8 + b]  = rsqrtf(a);
            g_misc[16 + b] = rsqrtf(c);
        }
    } else {
        // ── seg streaming path: gather-vg + smem-histogram design ──
        const float* segb = seg + (size_t)b * NCH * HWSZ;
        const int*   gtb  = gt  + (size_t)b * HWSZ;

        __shared__ float sh_hi[8][NCH + 1];   // per-warp inter histogram (+pad)
        __shared__ float sh_hc[8][NCH + 1];   // per-warp cnt   histogram
        if (lane < NCH + 1) { sh_hi[w][lane] = 0.f; sh_hc[w][lane] = 0.f; }
        __syncthreads();

        float psum[NCH];
#pragma unroll
        for (int c = 0; c < NCH; c++) psum[c] = 0.f;
        float focal = 0.f;

        const int tid0   = bx * blockDim.x + tid;
        const int stride = NSLOT * 256;

        for (int g = tid0; g < NGROUPS; g += stride) {
            const int px = g * 4;
            const int4 t4 = *(const int4*)(gtb + px);
            // direct gathers of the gt-channel values (same lines as the stream → L1 hits)
            float vg0 = segb[(size_t)t4.x * HWSZ + px + 0];
            float vg1 = segb[(size_t)t4.y * HWSZ + px + 1];
            float vg2 = segb[(size_t)t4.z * HWSZ + px + 2];
            float vg3 = segb[(size_t)t4.w * HWSZ + px + 3];

            float s0=0.f, s1=0.f, s2=0.f, s3=0.f;
#pragma unroll
            for (int c = 0; c < NCH; c++) {
                float4 p = *(const float4*)(segb + (size_t)c * HWSZ + px);
                s0 += fast_exp(p.x); s1 += fast_exp(p.y);
                s2 += fast_exp(p.z); s3 += fast_exp(p.w);
                psum[c] += (p.x + p.y) + (p.z + p.w);
            }

            // inter/cnt histograms via per-warp smem atomics (8 ATOMS/group)
            atomicAdd(&sh_hi[w][t4.x], vg0);  atomicAdd(&sh_hc[w][t4.x], 1.f);
            atomicAdd(&sh_hi[w][t4.y], vg1);  atomicAdd(&sh_hc[w][t4.y], 1.f);
            atomicAdd(&sh_hi[w][t4.z], vg2);  atomicAdd(&sh_hc[w][t4.z], 1.f);
            atomicAdd(&sh_hi[w][t4.w], vg3);  atomicAdd(&sh_hc[w][t4.w], 1.f);

            // focal: alpha*(1-p_t)^2 * (lse - v_gt)
            float eg0 = fast_exp(vg0), eg1 = fast_exp(vg1);
            float eg2 = fast_exp(vg2), eg3 = fast_exp(vg3);
            float ce0 = __logf(s0) - vg0, pt0 = __fdividef(eg0, s0);
            float ce1 = __logf(s1) - vg1, pt1 = __fdividef(eg1, s1);
            float ce2 = __logf(s2) - vg2, pt2 = __fdividef(eg2, s2);
            float ce3 = __logf(s3) - vg3, pt3 = __fdividef(eg3, s3);
            float o0 = 1.f - pt0, o1 = 1.f - pt1, o2 = 1.f - pt2, o3 = 1.f - pt3;
            focal += 0.25f * ((o0*o0*ce0 + o1*o1*ce1) + (o2*o2*ce2 + o3*o3*ce3));
        }

        // ── block reduction ──
        __shared__ float sh_ps[8][NCH + 1];
        __shared__ float sh_f[8];
#pragma unroll
        for (int c = 0; c < NCH; c++) {
            float p = psum[c];
#pragma unroll
            for (int o = 16; o > 0; o >>= 1) p += __shfl_down_sync(FULL, p, o);
            if (lane == 0) sh_ps[w][c] = p;
        }
        {
            float f = focal;
#pragma unroll
            for (int o = 16; o > 0; o >>= 1) f += __shfl_down_sync(FULL, f, o);
            if (lane == 0) sh_f[w] = f;
        }
        __syncthreads();
        if (tid < NCH) {
            float I = 0.f, P = 0.f, C = 0.f;
#pragma unroll
            for (int i = 0; i < 8; i++) {
                I += sh_hi[i][tid]; P += sh_ps[i][tid]; C += sh_hc[i][tid];
            }
            g_part[b][bx][tid]          = I;
            g_part[b][bx][NCH + tid]    = P;
            g_part[b][bx][2*NCH + tid]  = C;
        } else if (tid == NCH) {
            float f = 0.f;
#pragma unroll
            for (int i = 0; i < 8; i++) f += sh_f[i];
            g_part[b][bx][57] = f;
        }
    }

    // ── last-CTA-done: 440th arrival runs the finalize with its 256 threads ──
    __shared__ int sIsLast;
    __syncthreads();
    if (tid == 0) {
        __threadfence();
        int v = atomicAdd(&g_count, 1);
        sIsLast = (v == TOTAL_CTAS - 1) ? 1 : 0;
    }
    __syncthreads();
    if (!sIsLast) return;
    if (tid == 0) g_count = 0;           // reset for next graph replay
    __threadfence();

    __shared__ float sh_red[8][5];
    __shared__ float sh_blk[8];

    float vinv[8], tinv[8];
#pragma unroll
    for (int i = 0; i < 8; i++) { vinv[i] = g_misc[8 + i]; tinv[i] = g_misc[16 + i]; }

    // modal-balance accumulations (vf/tf L2-hot)
    float s_vn2 = 0.f, s_tn2 = 0.f, s_mu2v = 0.f, s_mu2t = 0.f, s_cross = 0.f;
#pragma unroll
    for (int it = 0; it < NDIM/256; it++) {
        int d = it * 256 + tid;
        float sumv = 0.f, sumt = 0.f;
#pragma unroll
        for (int bb = 0; bb < 8; bb++) {
            float vn = vf[bb*NDIM + d] * vinv[bb];
            float tn = tf[bb*NDIM + d] * tinv[bb];
            s_vn2  = fmaf(vn, vn, s_vn2);
            s_tn2  = fmaf(tn, tn, s_tn2);
            s_cross= fmaf(vn, tn, s_cross);
            sumv += vn; sumt += tn;
        }
        s_mu2v = fmaf(sumv, sumv, s_mu2v);
        s_mu2t = fmaf(sumt, sumt, s_mu2t);
    }
#pragma unroll
    for (int o = 16; o > 0; o >>= 1) {
        s_vn2  += __shfl_down_sync(FULL, s_vn2, o);
        s_tn2  += __shfl_down_sync(FULL, s_tn2, o);
        s_mu2v += __shfl_down_sync(FULL, s_mu2v, o);
        s_mu2t += __shfl_down_sync(FULL, s_mu2t, o);
        s_cross+= __shfl_down_sync(FULL, s_cross, o);
    }
    if (lane == 0) {
        sh_red[w][0] = s_vn2;  sh_red[w][1] = s_tn2;
        sh_red[w][2] = s_mu2v; sh_red[w][3] = s_mu2t; sh_red[w][4] = s_cross;
    }

    // dice term per (b,c) + focal partials → one block value
    float v = 0.f;
    if (tid < NB*NCH) {
        const int bb = tid / NCH, c = tid % NCH;
        float I = 0.f, P = 0.f, C = 0.f;
#pragma unroll
        for (int x = 0; x < NSLOT; x++) {
            I += g_part[bb][x][c];
            P += g_part[bb][x][NCH + c];
            C += g_part[bb][x][2*NCH + c];
        }
        v = (1.f - (2.f*I + 1e-5f) / (P + C + 1e-5f)) * (0.5f / (float)(NB*NCH));
    }
    {
        float f = 0.f;
#pragma unroll
        for (int s = tid; s < NB*NSLOT; s += 256)
            f += g_part[s / NSLOT][s % NSLOT][57];
        v = fmaf(f, 0.5f / ((float)NB * (float)HWSZ), v);
    }
#pragma unroll
    for (int o = 16; o > 0; o >>= 1) v += __shfl_down_sync(FULL, v, o);
    if (lane == 0) sh_blk[w] = v;
    __syncthreads();

    if (tid == 0) {
        float segv = 0.f;
#pragma unroll
        for (int i = 0; i < 8; i++) segv += sh_blk[i];

        float a0=0.f,a1=0.f,a2=0.f,a3=0.f,a4=0.f, ce=0.f;
#pragma unroll
        for (int i = 0; i < 8; i++) {
            a0 += sh_red[i][0]; a1 += sh_red[i][1]; a2 += sh_red[i][2];
            a3 += sh_red[i][3]; a4 += sh_red[i][4]; ce += g_misc[i];
        }
        ce *= 0.125f;
        const float BD = 8.f * (float)NDIM;
        float vcons = a0 / BD - a2 / (8.f * BD);
        float tcons = a1 / BD - a3 / (8.f * BD);
        float cross = 1.f - a4 * 0.125f;

        float mm0 = 0.f, mm1 = 0.f;
#pragma unroll
        for (int i = 0; i < 8; i++) { mm0 += mm[2*i]; mm1 += mm[2*i + 1]; }
        mm0 *= 0.125f; mm1 *= 0.125f;

        float e = (float)ep[0];
        float beta = 0.5f * __expf(e * -0.010050335853501441f);  // 0.5 * 0.99^e
        float mb = (1.f - beta) * vcons * mm0 + beta * tcons * mm1 + cross;

        out[0] = ce + 0.3f * mb + segv;
    }
}

extern "C" void kernel_launch(void* const* d_in, const int* in_sizes, int n_in,
                              void* d_out, int out_size) {
    const float* logits = (const float*)d_in[0];
    const int*   label  = (const int*)  d_in[1];
    const float* vfeat  = (const float*)d_in[2];
    const float* tfeat  = (const float*)d_in[3];
    const float* mmask  = (const float*)d_in[4];
    const float* seg    = (const float*)d_in[5];
    const int*   gt     = (const int*)  d_in[6];
    const int*   ep     = (const int*)  d_in[7];

    fused_kernel<<<dim3(NSLOT + 1, NB), 256>>>(seg, gt, logits, label,
                                               vfeat, tfeat, mmask, ep, (float*)d_out);
}

// round 10
// speedup vs baseline: 1.3918x; 1.3918x over previous
#include <cuda_runtime.h>

#define NB      8
#define NCH     19
#define HWSZ    (512*512)
#define NDIM    768
#define NCLS    1000
#define NSLOT   54
#define TOTAL_CTAS (NB * (NSLOT + 1))   // 440 CTAs : single wave @occ3 (148 SMs)
#define NGROUPS (HWSZ/4)

// per-block partials: [b][slot][ 0..18 inter | 19..37 psum | 38..56 cnt | 57 focal | pad ]
__device__ float g_part[NB][NSLOT][60];
__device__ float g_misc[24];            // ce[8] | vinv[8] | tinv[8]
__device__ int   g_count;               // static zero-init; last CTA resets it

__device__ __forceinline__ float fast_exp(float x) {
    // exp(x) = 2^(x*log2e); FMA-fused magic round; splice uses fz bits directly
    const float L2E = 1.4426950408889634f;
    float fz = fmaf(x, L2E, 12582912.0f);
    float fm = fz - 12582912.0f;
    float r  = fmaf(x, L2E, -fm);               // r in [-0.5, 0.5]
    float p  = 9.6181291e-3f;
    p = fmaf(p, r, 5.5504109e-2f);
    p = fmaf(p, r, 2.4022651e-1f);
    p = fmaf(p, r, 6.9314718e-1f);
    p = fmaf(p, r, 1.0f);
    return __int_as_float(__float_as_int(p) + (__float_as_int(fz) << 23));
}

__global__ __launch_bounds__(256, 3) void fused_kernel(
    const float* __restrict__ seg,    const int* __restrict__ gt,
    const float* __restrict__ logits, const int* __restrict__ label,
    const float* __restrict__ vf,     const float* __restrict__ tf,
    const float* __restrict__ mm,     const int* __restrict__ ep,
    float* __restrict__ out)
{
    const int b  = blockIdx.y;
    const int bx = blockIdx.x;
    const unsigned FULL = 0xffffffffu;
    const int tid  = threadIdx.x;
    const int lane = tid & 31;
    const int w    = tid >> 5;

    // per-thread private histograms: stride 19 (odd) → conflict-free banks
    __shared__ float          s_int[256 * NCH];   // 19456 B
    __shared__ unsigned short s_cnt[256 * NCH];   //  9728 B
    __shared__ float sh_oI[8][NCH], sh_oC[8][NCH], sh_ps[8][NCH], sh_f[8];

    if (bx == NSLOT) {
        // ── misc CTA (one per batch row): CE + feature norms ──
        float ce_p = 0.f, sv = 0.f, st = 0.f;
        if (tid < NCLS/4) {
            float4 L = ((const float4*)(logits + b*NCLS))[tid];
            ce_p = (__expf(L.x) + __expf(L.y)) + (__expf(L.z) + __expf(L.w));
        }
        if (tid < NDIM/4) {
            float4 V = ((const float4*)(vf + b*NDIM))[tid];
            sv = fmaf(V.x,V.x, fmaf(V.y,V.y, fmaf(V.z,V.z, V.w*V.w)));
            float4 T = ((const float4*)(tf + b*NDIM))[tid];
            st = fmaf(T.x,T.x, fmaf(T.y,T.y, fmaf(T.z,T.z, T.w*T.w)));
        }
#pragma unroll
        for (int o = 16; o > 0; o >>= 1) {
            ce_p += __shfl_down_sync(FULL, ce_p, o);
            sv   += __shfl_down_sync(FULL, sv, o);
            st   += __shfl_down_sync(FULL, st, o);
        }
        __shared__ float shm[8][3];
        if (lane == 0) { shm[w][0] = ce_p; shm[w][1] = sv; shm[w][2] = st; }
        __syncthreads();
        if (tid == 0) {
            float s = 0.f, a = 0.f, c = 0.f;
#pragma unroll
            for (int i = 0; i < 8; i++) { s += shm[i][0]; a += shm[i][1]; c += shm[i][2]; }
            g_misc[b]      = __logf(s) - logits[b*NCLS + label[b]];
            g_misc[8 + b]  = rsqrtf(a);
            g_misc[16 + b] = rsqrtf(c);
        }
    } else {
        // ── seg streaming path: gather-vg + private smem histograms ──
        const float* segb = seg + (size_t)b * NCH * HWSZ;
        const int*   gtb  = gt  + (size_t)b * HWSZ;

        const int hbase = tid * NCH;
#pragma unroll
        for (int c = 0; c < NCH; c++) { s_int[hbase + c] = 0.f; s_cnt[hbase + c] = 0; }

        float psum[NCH];
#pragma unroll
        for (int c = 0; c < NCH; c++) psum[c] = 0.f;
        float focal = 0.f;

        const int tid0   = bx * blockDim.x + tid;
        const int stride = NSLOT * 256;

        for (int g = tid0; g < NGROUPS; g += stride) {
            const int px = g * 4;
            const int4 t4 = *(const int4*)(gtb + px);
            // direct gathers of the gt-channel values (same lines as the stream)
            float vg0 = __ldg(segb + (size_t)t4.x * HWSZ + px + 0);
            float vg1 = __ldg(segb + (size_t)t4.y * HWSZ + px + 1);
            float vg2 = __ldg(segb + (size_t)t4.z * HWSZ + px + 2);
            float vg3 = __ldg(segb + (size_t)t4.w * HWSZ + px + 3);

            float s0=0.f, s1=0.f, s2=0.f, s3=0.f;
#pragma unroll
            for (int c = 0; c < NCH; c++) {
                float4 p = *(const float4*)(segb + (size_t)c * HWSZ + px);
                s0 += fast_exp(p.x); s1 += fast_exp(p.y);
                s2 += fast_exp(p.z); s3 += fast_exp(p.w);
                psum[c] += (p.x + p.y) + (p.z + p.w);
            }

            // private histogram updates (shared pipe, conflict-free, race-free)
            s_int[hbase + t4.x] += vg0;  s_cnt[hbase + t4.x]++;
            s_int[hbase + t4.y] += vg1;  s_cnt[hbase + t4.y]++;
            s_int[hbase + t4.z] += vg2;  s_cnt[hbase + t4.z]++;
            s_int[hbase + t4.w] += vg3;  s_cnt[hbase + t4.w]++;

            // focal: alpha*(1-p_t)^2 * (lse - v_gt)
            float eg0 = fast_exp(vg0), eg1 = fast_exp(vg1);
            float eg2 = fast_exp(vg2), eg3 = fast_exp(vg3);
            float ce0 = __logf(s0) - vg0, pt0 = __fdividef(eg0, s0);
            float ce1 = __logf(s1) - vg1, pt1 = __fdividef(eg1, s1);
            float ce2 = __logf(s2) - vg2, pt2 = __fdividef(eg2, s2);
            float ce3 = __logf(s3) - vg3, pt3 = __fdividef(eg3, s3);
            float o0 = 1.f - pt0, o1 = 1.f - pt1, o2 = 1.f - pt2, o3 = 1.f - pt3;
            focal += 0.25f * ((o0*o0*ce0 + o1*o1*ce1) + (o2*o2*ce2 + o3*o3*ce3));
        }

        // ── block reduction: per-channel warp folds, then cross-warp ──
#pragma unroll
        for (int c = 0; c < NCH; c++) {
            float I = s_int[hbase + c];
            float C = (float)s_cnt[hbase + c];
            float P = psum[c];
#pragma unroll
            for (int o = 16; o > 0; o >>= 1) {
                I += __shfl_down_sync(FULL, I, o);
                C += __shfl_down_sync(FULL, C, o);
                P += __shfl_down_sync(FULL, P, o);
            }
            if (lane == 0) { sh_oI[w][c] = I; sh_oC[w][c] = C; sh_ps[w][c] = P; }
        }
        {
            float f = focal;
#pragma unroll
            for (int o = 16; o > 0; o >>= 1) f += __shfl_down_sync(FULL, f, o);
            if (lane == 0) sh_f[w] = f;
        }
        __syncthreads();
        if (tid < NCH) {
            float I = 0.f, P = 0.f, C = 0.f;
#pragma unroll
            for (int i = 0; i < 8; i++) {
                I += sh_oI[i][tid]; P += sh_ps[i][tid]; C += sh_oC[i][tid];
            }
            g_part[b][bx][tid]          = I;
            g_part[b][bx][NCH + tid]    = P;
            g_part[b][bx][2*NCH + tid]  = C;
        } else if (tid == NCH) {
            float f = 0.f;
#pragma unroll
            for (int i = 0; i < 8; i++) f += sh_f[i];
            g_part[b][bx][57] = f;
        }
    }

    // ── last-CTA-done: 440th arrival runs the finalize with its 256 threads ──
    __shared__ int sIsLast;
    __syncthreads();
    if (tid == 0) {
        __threadfence();
        int v = atomicAdd(&g_count, 1);
        sIsLast = (v == TOTAL_CTAS - 1) ? 1 : 0;
    }
    __syncthreads();
    if (!sIsLast) return;
    if (tid == 0) g_count = 0;           // reset for next graph replay
    __threadfence();

    __shared__ float sh_red[8][5];
    __shared__ float sh_blk[8];

    float vinv[8], tinv[8];
#pragma unroll
    for (int i = 0; i < 8; i++) { vinv[i] = g_misc[8 + i]; tinv[i] = g_misc[16 + i]; }

    // modal-balance accumulations (vf/tf L2-hot)
    float s_vn2 = 0.f, s_tn2 = 0.f, s_mu2v = 0.f, s_mu2t = 0.f, s_cross = 0.f;
#pragma unroll
    for (int it = 0; it < NDIM/256; it++) {
        int d = it * 256 + tid;
        float sumv = 0.f, sumt = 0.f;
#pragma unroll
        for (int bb = 0; bb < 8; bb++) {
            float vn = vf[bb*NDIM + d] * vinv[bb];
            float tn = tf[bb*NDIM + d] * tinv[bb];
            s_vn2  = fmaf(vn, vn, s_vn2);
            s_tn2  = fmaf(tn, tn, s_tn2);
            s_cross= fmaf(vn, tn, s_cross);
            sumv += vn; sumt += tn;
        }
        s_mu2v = fmaf(sumv, sumv, s_mu2v);
        s_mu2t = fmaf(sumt, sumt, s_mu2t);
    }
#pragma unroll
    for (int o = 16; o > 0; o >>= 1) {
        s_vn2  += __shfl_down_sync(FULL, s_vn2, o);
        s_tn2  += __shfl_down_sync(FULL, s_tn2, o);
        s_mu2v += __shfl_down_sync(FULL, s_mu2v, o);
        s_mu2t += __shfl_down_sync(FULL, s_mu2t, o);
        s_cross+= __shfl_down_sync(FULL, s_cross, o);
    }
    if (lane == 0) {
        sh_red[w][0] = s_vn2;  sh_red[w][1] = s_tn2;
        sh_red[w][2] = s_mu2v; sh_red[w][3] = s_mu2t; sh_red[w][4] = s_cross;
    }

    // dice term per (b,c) + focal partials → one block value
    float v = 0.f;
    if (tid < NB*NCH) {
        const int bb = tid / NCH, c = tid % NCH;
        float I = 0.f, P = 0.f, C = 0.f;
#pragma unroll
        for (int x = 0; x < NSLOT; x++) {
            I += g_part[bb][x][c];
            P += g_part[bb][x][NCH + c];
            C += g_part[bb][x][2*NCH + c];
        }
        v = (1.f - (2.f*I + 1e-5f) / (P + C + 1e-5f)) * (0.5f / (float)(NB*NCH));
    }
    {
        float f = 0.f;
#pragma unroll
        for (int s = tid; s < NB*NSLOT; s += 256)
            f += g_part[s / NSLOT][s % NSLOT][57];
        v = fmaf(f, 0.5f / ((float)NB * (float)HWSZ), v);
    }
#pragma unroll
    for (int o = 16; o > 0; o >>= 1) v += __shfl_down_sync(FULL, v, o);
    if (lane == 0) sh_blk[w] = v;
    __syncthreads();

    if (tid == 0) {
        float segv = 0.f;
#pragma unroll
        for (int i = 0; i < 8; i++) segv += sh_blk[i];

        float a0=0.f,a1=0.f,a2=0.f,a3=0.f,a4=0.f, ce=0.f;
#pragma unroll
        for (int i = 0; i < 8; i++) {
            a0 += sh_red[i][0]; a1 += sh_red[i][1]; a2 += sh_red[i][2];
            a3 += sh_red[i][3]; a4 += sh_red[i][4]; ce += g_misc[i];
        }
        ce *= 0.125f;
        const float BD = 8.f * (float)NDIM;
        float vcons = a0 / BD - a2 / (8.f * BD);
        float tcons = a1 / BD - a3 / (8.f * BD);
        float cross = 1.f - a4 * 0.125f;

        float mm0 = 0.f, mm1 = 0.f;
#pragma unroll
        for (int i = 0; i < 8; i++) { mm0 += mm[2*i]; mm1 += mm[2*i + 1]; }
        mm0 *= 0.125f; mm1 *= 0.125f;

        float e = (float)ep[0];
        float beta = 0.5f * __expf(e * -0.010050335853501441f);  // 0.5 * 0.99^e
        float mb = (1.f - beta) * vcons * mm0 + beta * tcons * mm1 + cross;

        out[0] = ce + 0.3f * mb + segv;
    }
}

extern "C" void kernel_launch(void* const* d_in, const int* in_sizes, int n_in,
                              void* d_out, int out_size) {
    const float* logits = (const float*)d_in[0];
    const int*   label  = (const int*)  d_in[1];
    const float* vfeat  = (const float*)d_in[2];
    const float* tfeat  = (const float*)d_in[3];
    const float* mmask  = (const float*)d_in[4];
    const float* seg    = (const float*)d_in[5];
    const int*   gt     = (const int*)  d_in[6];
    const int*   ep     = (const int*)  d_in[7];

    fused_kernel<<<dim3(NSLOT + 1, NB), 256>>>(seg, gt, logits, label,
                                               vfeat, tfeat, mmask, ep, (float*)d_out);
}